// round 2
// baseline (speedup 1.0000x reference)
#include <cuda_runtime.h>
#include <cstdint>

// BinCat: idx = sum_j (1 - x[b,i,j]) * 2^(L-1-j), out[b,i,:] = cats[idx,:]
// x:    (4096, 16, 20) int32  (values 0/1)
// cats: (2^20, 64) float32
// out:  (4096, 16, 64) float32
//
// One warp per output row. Lanes 0..19 compute disjoint bit contributions,
// combined via __reduce_or_sync (bits are disjoint so OR == ADD).
// All 32 lanes then copy the 256B cats row as float2 (fully coalesced,
// 256B-aligned -> 2 full 128B lines, no wasted sectors).

static constexpr int LENGTH = 20;
static constexpr int DIM    = 64;

__global__ void __launch_bounds__(256)
bincat_gather_kernel(const int* __restrict__ x,
                     const float* __restrict__ cats,
                     float* __restrict__ out,
                     int nrows)
{
    const int gtid    = blockIdx.x * blockDim.x + threadIdx.x;
    const int warp_id = gtid >> 5;          // one warp per (b, i) row
    const int lane    = gtid & 31;
    if (warp_id >= nrows) return;

    // --- compute 20-bit index ---
    const int* xr = x + (size_t)warp_id * LENGTH;
    unsigned contrib = 0u;
    if (lane < LENGTH) {
        // x is 0/1; (1 - x) selects the bit. Weight 2^(19 - lane).
        contrib = (unsigned)(1 - xr[lane]) << (LENGTH - 1 - lane);
    }
    const unsigned idx = __reduce_or_sync(0xffffffffu, contrib);

    // --- gather 64-float row (256 B) ---
    const float2* __restrict__ src =
        reinterpret_cast<const float2*>(cats + (size_t)idx * DIM);
    float2* __restrict__ dst =
        reinterpret_cast<float2*>(out + (size_t)warp_id * DIM);

    dst[lane] = __ldg(&src[lane]);
}

extern "C" void kernel_launch(void* const* d_in, const int* in_sizes, int n_in,
                              void* d_out, int out_size)
{
    const int*   x    = (const int*)d_in[0];    // (B, I, 20) int32
    const float* cats = (const float*)d_in[1];  // (2^20, 64) float32
    float*       out  = (float*)d_out;          // (B, I, 64) float32

    const int nrows = in_sizes[0] / LENGTH;     // B * I = 65536

    const int threads = 256;                    // 8 warps per block
    const int warps_per_block = threads / 32;
    const int blocks = (nrows + warps_per_block - 1) / warps_per_block;

    bincat_gather_kernel<<<blocks, threads>>>(x, cats, out, nrows);
}